// round 2
// baseline (speedup 1.0000x reference)
#include <cuda_runtime.h>
#include <cuda_bf16.h>

// Fixed problem shapes
constexpr int NN    = 50000;   // nodes
constexpr int F_IN  = 64;
constexpr int HEADS = 4;
constexpr int HID   = 32;
constexpr int C1    = HEADS * HID;  // 128
constexpr int C2    = HID;          // 32
constexpr int CLS   = 3;

// ---------------- scratch (device globals; no allocation allowed) ----------
__device__ __align__(16) float g_h1[NN * C1];
__device__ float g_asrc1[NN * HEADS];
__device__ float g_adst1[NN * HEADS];
__device__ float g_denom1[NN * HEADS];
__device__ __align__(16) float g_out1[NN * C1];
__device__ __align__(16) float g_h2[NN * C2];
__device__ float g_asrc2[NN];
__device__ float g_adst2[NN];
__device__ float g_denom2[NN];
__device__ __align__(16) float g_out2[NN * C2];
__device__ float g_accum[C2];
__device__ int   g_ei64;   // 1 if edge_index arrived as int64

// ---------------- detect edge_index dtype -----------------------------------
__global__ void k_detect(const int* __restrict__ ei) {
    if (threadIdx.x == 0) {
        int all_zero = 1;
        #pragma unroll 8
        for (int i = 1; i < 512; i += 2)
            if (ei[i] != 0) { all_zero = 0; break; }
        g_ei64 = all_zero;
    }
}

__device__ __forceinline__ void load_edge(const int* ei, int idx, int E,
                                          int& src, int& dst) {
    if (g_ei64) {
        const long long* e64 = (const long long*)ei;
        src = (int)e64[idx];
        dst = (int)e64[E + idx];
    } else {
        src = ei[idx];
        dst = ei[E + idx];
    }
}

// ---------------- init: zero all accumulators ------------------------------
__global__ void k_init() {
    int i = blockIdx.x * blockDim.x + threadIdx.x;
    int stride = gridDim.x * blockDim.x;
    for (; i < NN * C1; i += stride) {
        g_out1[i] = 0.f;
        if (i < NN * C2) g_out2[i] = 0.f;
        if (i < NN * HEADS) g_denom1[i] = 0.f;
        if (i < NN) g_denom2[i] = 0.f;
        if (i < C2) g_accum[i] = 0.f;
    }
}

// ---------------- K1: h1 = x @ W1 ; a_src1/a_dst1 ---------------------------
__global__ void k_gemm1(const float* __restrict__ x, const float* __restrict__ W1,
                        const float* __restrict__ attS, const float* __restrict__ attD,
                        int n) {
    __shared__ float Wsh[F_IN * C1];   // 32 KB
    __shared__ float xsh[32 * F_IN];   // 8 KB
    int t = threadIdx.x;               // 0..127 (output column)
    for (int i = t; i < F_IN * C1; i += 128) Wsh[i] = W1[i];
    int n0 = blockIdx.x * 32;
    int nmax = min(32, n - n0);
    for (int i = t; i < nmax * F_IN; i += 128) xsh[i] = x[n0 * F_IN + i];
    __syncthreads();

    float aS = attS[t], aD = attD[t];
    int lane = t & 31, w = t >> 5;     // warp w == head w
    for (int nn = 0; nn < nmax; nn++) {
        float acc = 0.f;
        #pragma unroll
        for (int k = 0; k < F_IN; k++)
            acc += xsh[nn * F_IN + k] * Wsh[k * C1 + t];
        g_h1[(n0 + nn) * C1 + t] = acc;
        float vs = acc * aS, vd = acc * aD;
        #pragma unroll
        for (int o = 16; o > 0; o >>= 1) {
            vs += __shfl_down_sync(0xffffffffu, vs, o);
            vd += __shfl_down_sync(0xffffffffu, vd, o);
        }
        if (lane == 0) {
            g_asrc1[(n0 + nn) * HEADS + w] = vs;
            g_adst1[(n0 + nn) * HEADS + w] = vd;
        }
    }
}

// ---------------- K2: edge pass, layer 1 (warp per edge) -------------------
// alpha = exp(e)/sum exp(e): max-subtraction omitted (e bounded, exact ratio)
__global__ void k_edge1(const int* __restrict__ ei, int E, int ET) {
    int gw = (blockIdx.x * blockDim.x + threadIdx.x) >> 5;
    if (gw >= ET) return;
    int lane = threadIdx.x & 31;
    int src, dst;
    if (gw < E) load_edge(ei, gw, E, src, dst);
    else        src = dst = gw - E;                           // self-loop

    int h = lane >> 3;                                        // 8 lanes/head
    float e = g_asrc1[src * HEADS + h] + g_adst1[dst * HEADS + h];
    e = fmaxf(e, 0.2f * e);                                   // leaky_relu
    float p = __expf(e);
    if ((lane & 7) == 0) atomicAdd(&g_denom1[dst * HEADS + h], p);

    float4 v = reinterpret_cast<const float4*>(g_h1)[src * 32 + lane];
    v.x *= p; v.y *= p; v.z *= p; v.w *= p;
    atomicAdd(reinterpret_cast<float4*>(g_out1) + dst * 32 + lane, v);
}

// ---------------- K3: finalize layer 1 + GEMM2 + attn coeffs ---------------
__global__ void k_node1(const float* __restrict__ W2, const float* __restrict__ b1,
                        const float* __restrict__ attS2, const float* __restrict__ attD2,
                        int n) {
    __shared__ float W2sh[C1 * C2];  // 16 KB
    __shared__ float hsh[8 * C1];    // 4 KB
    int tx = threadIdx.x, ty = threadIdx.y;
    int t = ty * 32 + tx;
    for (int i = t; i < C1 * C2; i += 256) W2sh[i] = W2[i];
    int n0 = blockIdx.x * 8;
    for (int i = t; i < 8 * C1; i += 256) {
        int nn = i >> 7, k = i & 127;
        int node = n0 + nn;
        float v = 0.f;
        if (node < n) {
            v = g_out1[node * C1 + k] / g_denom1[node * HEADS + (k >> 5)] + b1[k];
            v = v > 0.f ? v : expm1f(v);                      // ELU
        }
        hsh[i] = v;
    }
    __syncthreads();
    int node = n0 + ty;
    if (node >= n) return;
    float acc = 0.f;
    #pragma unroll
    for (int k = 0; k < C1; k++)
        acc += hsh[ty * C1 + k] * W2sh[k * C2 + tx];
    g_h2[node * C2 + tx] = acc;
    float vs = acc * attS2[tx], vd = acc * attD2[tx];
    #pragma unroll
    for (int o = 16; o > 0; o >>= 1) {
        vs += __shfl_down_sync(0xffffffffu, vs, o);
        vd += __shfl_down_sync(0xffffffffu, vd, o);
    }
    if (tx == 0) { g_asrc2[node] = vs; g_adst2[node] = vd; }
}

// ---------------- K4: edge pass, layer 2 (8 threads per edge) --------------
__global__ void k_edge2(const int* __restrict__ ei, int E, int ET) {
    long long tid = (long long)blockIdx.x * blockDim.x + threadIdx.x;
    int ge = (int)(tid >> 3);
    if (ge >= ET) return;
    int j = (int)(tid & 7);
    int src, dst;
    if (ge < E) load_edge(ei, ge, E, src, dst);
    else        src = dst = ge - E;

    float e = g_asrc2[src] + g_adst2[dst];
    e = fmaxf(e, 0.2f * e);
    float p = __expf(e);
    if (j == 0) atomicAdd(&g_denom2[dst], p);

    float4 v = reinterpret_cast<const float4*>(g_h2)[src * 8 + j];
    v.x *= p; v.y *= p; v.z *= p; v.w *= p;
    atomicAdd(reinterpret_cast<float4*>(g_out2) + dst * 8 + j, v);
}

// ---------------- K5: finalize layer 2 + global sum ------------------------
__global__ void k_final(const float* __restrict__ b2, int n) {
    __shared__ float sd[256];
    int t = threadIdx.x, c = t & 31, g = t >> 5;  // 8 node-groups of 32 lanes
    float local = 0.f;
    for (int node = blockIdx.x * 8 + g; node < n; node += gridDim.x * 8)
        local += g_out2[node * C2 + c] / g_denom2[node] + b2[c];
    sd[t] = local;
    __syncthreads();
    if (t < 128) sd[t] += sd[t + 128];
    __syncthreads();
    if (t < 64) sd[t] += sd[t + 64];
    __syncthreads();
    if (t < 32) {
        float s = sd[t] + sd[t + 32];
        atomicAdd(&g_accum[c], s);
    }
}

// ---------------- K6: mean -> logits -> softmax -----------------------------
__global__ void k_out(const float* __restrict__ linW, const float* __restrict__ linb,
                      float* __restrict__ out, int n) {
    if (threadIdx.x == 0) {
        float logits[CLS];
        float invn = 1.0f / (float)n;
        for (int j = 0; j < CLS; j++) {
            float s = linb[j];
            for (int c = 0; c < C2; c++)
                s += (g_accum[c] * invn) * linW[c * CLS + j];
            logits[j] = s;
        }
        float m = fmaxf(logits[0], fmaxf(logits[1], logits[2]));
        float e0 = expf(logits[0] - m);
        float e1 = expf(logits[1] - m);
        float e2 = expf(logits[2] - m);
        float s = e0 + e1 + e2;
        out[0] = e0 / s; out[1] = e1 / s; out[2] = e2 / s;
    }
}

// ---------------- launcher ---------------------------------------------------
extern "C" void kernel_launch(void* const* d_in, const int* in_sizes, int n_in,
                              void* d_out, int out_size) {
    const float* x        = (const float*)d_in[0];
    const float* W1       = (const float*)d_in[1];
    const float* att_src1 = (const float*)d_in[2];
    const float* att_dst1 = (const float*)d_in[3];
    const float* b1       = (const float*)d_in[4];
    const float* W2       = (const float*)d_in[5];
    const float* att_src2 = (const float*)d_in[6];
    const float* att_dst2 = (const float*)d_in[7];
    const float* b2       = (const float*)d_in[8];
    const float* linW     = (const float*)d_in[9];
    const float* linb     = (const float*)d_in[10];
    const int*   ei       = (const int*)d_in[11];

    int n  = in_sizes[0] / F_IN;       // 50000
    int E  = in_sizes[11] / 2;         // 800000
    int ET = E + n;                    // edges + self-loops
    float* out = (float*)d_out;

    k_detect<<<1, 32>>>(ei);
    k_init<<<4096, 256>>>();

    k_gemm1<<<(n + 31) / 32, 128>>>(x, W1, att_src1, att_dst1, n);

    {
        long long threads = (long long)ET * 32;
        int blocks = (int)((threads + 255) / 256);
        k_edge1<<<blocks, 256>>>(ei, E, ET);
    }

    {
        dim3 bd(32, 8);
        k_node1<<<(n + 7) / 8, bd>>>(W2, b1, att_src2, att_dst2, n);
    }

    {
        long long threads = (long long)ET * 8;
        int blocks = (int)((threads + 255) / 256);
        k_edge2<<<blocks, 256>>>(ei, E, ET);
    }

    k_final<<<512, 256>>>(b2, n);

    k_out<<<1, 32>>>(linW, linb, out, n);
}

// round 3
// speedup vs baseline: 1.5185x; 1.5185x over previous
#include <cuda_runtime.h>
#include <cuda_bf16.h>

// Fixed problem shapes
constexpr int NN    = 50000;   // nodes
constexpr int EE    = 800000;  // edges (before self-loops)
constexpr int ETT   = EE + NN; // with self-loops
constexpr int F_IN  = 64;
constexpr int HEADS = 4;
constexpr int HID   = 32;
constexpr int C1    = HEADS * HID;  // 128
constexpr int C2    = HID;          // 32
constexpr int CLS   = 3;

// ---------------- scratch (device globals) ----------------------------------
__device__ __align__(16) float g_h1[NN * C1];
__device__ float g_asrc1[NN * HEADS];
__device__ float g_adst1[NN * HEADS];
__device__ __align__(16) float g_out1[NN * C1];   // normalized layer-1 aggregate
__device__ __align__(16) float g_h2[NN * C2];
__device__ float g_asrc2[NN];
__device__ float g_adst2[NN];
__device__ __align__(16) float g_out2[NN * C2];   // normalized layer-2 aggregate
__device__ float g_accum[C2];
__device__ int   g_ei64;

// CSR scratch
__device__ int g_deg[NN];
__device__ int g_off[NN];
__device__ int g_cursor[NN];
__device__ int g_bsum[256];
__device__ int g_bbase[256];
__device__ int g_sorted[ETT];

// ---------------- dtype detect ----------------------------------------------
__global__ void k_detect(const int* __restrict__ ei) {
    if (threadIdx.x == 0) {
        int all_zero = 1;
        for (int i = 1; i < 512; i += 2)
            if (ei[i] != 0) { all_zero = 0; break; }
        g_ei64 = all_zero;
    }
}

__device__ __forceinline__ void load_edge(const int* ei, int idx, int E,
                                          int& src, int& dst) {
    if (g_ei64) {
        const long long* e64 = (const long long*)ei;
        src = (int)e64[idx];
        dst = (int)e64[E + idx];
    } else {
        src = ei[idx];
        dst = ei[E + idx];
    }
}

// ---------------- init -------------------------------------------------------
__global__ void k_init(int n) {
    int i = blockIdx.x * blockDim.x + threadIdx.x;
    int stride = gridDim.x * blockDim.x;
    for (; i < n; i += stride) {
        g_deg[i] = 0;
        if (i < C2) g_accum[i] = 0.f;
        if (i < 256) { g_bsum[i] = 0; g_bbase[i] = 0; }
    }
}

// ---------------- CSR build --------------------------------------------------
__global__ void k_hist(const int* __restrict__ ei, int E, int ET) {
    int i = blockIdx.x * blockDim.x + threadIdx.x;
    if (i >= ET) return;
    int src, dst;
    if (i < E) load_edge(ei, i, E, src, dst);
    else       dst = i - E;
    atomicAdd(&g_deg[dst], 1);
}

__global__ void k_scan1(int n) {
    __shared__ int s[256];
    int i = blockIdx.x * 256 + threadIdx.x;
    int v = (i < n) ? g_deg[i] : 0;
    s[threadIdx.x] = v;
    __syncthreads();
    for (int o = 1; o < 256; o <<= 1) {
        int t2 = (threadIdx.x >= o) ? s[threadIdx.x - o] : 0;
        __syncthreads();
        s[threadIdx.x] += t2;
        __syncthreads();
    }
    if (i < n) g_off[i] = s[threadIdx.x] - v;            // exclusive
    if (threadIdx.x == 255) g_bsum[blockIdx.x] = s[255]; // block total
}

__global__ void k_scan2(int nb) {
    __shared__ int s[256];
    int t = threadIdx.x;
    int v = (t < nb) ? g_bsum[t] : 0;
    s[t] = v;
    __syncthreads();
    for (int o = 1; o < 256; o <<= 1) {
        int t2 = (t >= o) ? s[t - o] : 0;
        __syncthreads();
        s[t] += t2;
        __syncthreads();
    }
    g_bbase[t] = s[t] - v;   // exclusive
}

__global__ void k_scan3(int n) {
    int i = blockIdx.x * 256 + threadIdx.x;
    if (i < n) {
        int o = g_off[i] + g_bbase[blockIdx.x];
        g_off[i] = o;
        g_cursor[i] = o;
    }
}

__global__ void k_scatter(const int* __restrict__ ei, int E, int ET) {
    int i = blockIdx.x * blockDim.x + threadIdx.x;
    if (i >= ET) return;
    int src, dst;
    if (i < E) load_edge(ei, i, E, src, dst);
    else       src = dst = i - E;
    int pos = atomicAdd(&g_cursor[dst], 1);
    g_sorted[pos] = src;
}

// ---------------- K1: h1 = x @ W1 ; attn coeffs (W in registers) ------------
__global__ void __launch_bounds__(128) k_gemm1(
        const float* __restrict__ x, const float* __restrict__ W1,
        const float* __restrict__ attS, const float* __restrict__ attD, int n) {
    int t = threadIdx.x;   // output column 0..127
    float w[F_IN];
    #pragma unroll
    for (int k = 0; k < F_IN; k++) w[k] = W1[k * C1 + t];

    __shared__ float4 xsh[64 * 16];    // 64 nodes x 64 feats
    int n0 = blockIdx.x * 64;
    const float4* x4 = (const float4*)x;
    for (int i = t; i < 64 * 16; i += 128) {
        int node = n0 + (i >> 4);
        xsh[i] = (node < n) ? x4[node * 16 + (i & 15)] : make_float4(0.f, 0.f, 0.f, 0.f);
    }
    __syncthreads();

    float aS = attS[t], aD = attD[t];
    int lane = t & 31, wi = t >> 5;
    int nmax = min(64, n - n0);
    for (int nn = 0; nn < nmax; nn++) {
        float a0 = 0.f, a1 = 0.f, a2 = 0.f, a3 = 0.f;
        #pragma unroll
        for (int k4 = 0; k4 < 16; k4++) {
            float4 xv = xsh[nn * 16 + k4];
            a0 += xv.x * w[k4 * 4 + 0];
            a1 += xv.y * w[k4 * 4 + 1];
            a2 += xv.z * w[k4 * 4 + 2];
            a3 += xv.w * w[k4 * 4 + 3];
        }
        float acc = (a0 + a1) + (a2 + a3);
        g_h1[(n0 + nn) * C1 + t] = acc;
        float vs = acc * aS, vd = acc * aD;
        #pragma unroll
        for (int o = 16; o > 0; o >>= 1) {
            vs += __shfl_down_sync(0xffffffffu, vs, o);
            vd += __shfl_down_sync(0xffffffffu, vd, o);
        }
        if (lane == 0) {
            g_asrc1[(n0 + nn) * HEADS + wi] = vs;
            g_adst1[(n0 + nn) * HEADS + wi] = vd;
        }
    }
}

// ---------------- K2: edge pass 1, CSR, warp per destination ----------------
__global__ void k_edge1(int n) {
    int gw = (blockIdx.x * blockDim.x + threadIdx.x) >> 5;
    if (gw >= n) return;
    int lane = threadIdx.x & 31;
    int h = lane >> 3;
    float aD = g_adst1[gw * HEADS + h];
    int start = g_off[gw], deg = g_deg[gw];

    float4 acc = make_float4(0.f, 0.f, 0.f, 0.f);
    float psum = 0.f;
    for (int i = 0; i < deg; i += 8) {
        int myj = i + lane;
        int s = (lane < 8 && myj < deg) ? g_sorted[start + myj] : -1;
        #pragma unroll
        for (int j = 0; j < 8; j++) {
            int src = __shfl_sync(0xffffffffu, s, j);
            if (src >= 0) {
                float e = g_asrc1[src * HEADS + h] + aD;
                e = fmaxf(e, 0.2f * e);
                float p = __expf(e);
                float4 v = reinterpret_cast<const float4*>(g_h1)[src * 32 + lane];
                acc.x += p * v.x; acc.y += p * v.y;
                acc.z += p * v.z; acc.w += p * v.w;
                psum += p;
            }
        }
    }
    float inv = 1.0f / psum;
    acc.x *= inv; acc.y *= inv; acc.z *= inv; acc.w *= inv;
    reinterpret_cast<float4*>(g_out1)[gw * 32 + lane] = acc;
}

// ---------------- K3: bias+ELU, GEMM2 (W2 k-chunks in regs), attn coeffs ----
__global__ void __launch_bounds__(256) k_node1(
        const float* __restrict__ W2, const float* __restrict__ b1,
        const float* __restrict__ attS2, const float* __restrict__ attD2, int n) {
    int tx = threadIdx.x;        // col 0..31
    int ty = threadIdx.y;        // k-chunk 0..7 (16 k each)
    int t = ty * 32 + tx;

    float w2r[16];
    #pragma unroll
    for (int k = 0; k < 16; k++) w2r[k] = W2[(ty * 16 + k) * C2 + tx];

    __shared__ float hsh[16 * C1];      // 8 KB  (16 nodes)
    __shared__ float ps[8][16][32];     // 16 KB partials

    int n0 = blockIdx.x * 16;
    for (int i = t; i < 16 * C1; i += 256) {
        int nn = i >> 7, k = i & 127;
        int node = n0 + nn;
        float v = 0.f;
        if (node < n) {
            v = g_out1[node * C1 + k] + b1[k];
            v = v > 0.f ? v : expm1f(v);
        }
        hsh[i] = v;
    }
    __syncthreads();

    const float4* h4 = (const float4*)hsh;
    for (int nn = 0; nn < 16; nn++) {
        float acc = 0.f;
        #pragma unroll
        for (int k4 = 0; k4 < 4; k4++) {
            float4 hv = h4[nn * 32 + ty * 4 + k4];
            acc += hv.x * w2r[k4 * 4 + 0] + hv.y * w2r[k4 * 4 + 1]
                 + hv.z * w2r[k4 * 4 + 2] + hv.w * w2r[k4 * 4 + 3];
        }
        ps[ty][nn][tx] = acc;
    }
    __syncthreads();

    // reduce over k-chunks; thread t owns (node=t>>5 [+8], col=t&31)
    float aS = attS2[tx], aD = attD2[tx];
    #pragma unroll
    for (int pp = 0; pp < 2; pp++) {
        int nn = pp * 8 + (t >> 5);
        int col = tx;
        float s = 0.f;
        #pragma unroll
        for (int j = 0; j < 8; j++) s += ps[j][nn][col];
        int node = n0 + nn;
        float vs = s * aS, vd = s * aD;
        #pragma unroll
        for (int o = 16; o > 0; o >>= 1) {
            vs += __shfl_down_sync(0xffffffffu, vs, o);
            vd += __shfl_down_sync(0xffffffffu, vd, o);
        }
        if (node < n) {
            g_h2[node * C2 + col] = s;
            if (col == 0) { g_asrc2[node] = vs; g_adst2[node] = vd; }
        }
    }
}

// ---------------- K4: edge pass 2, CSR, warp per destination ----------------
__global__ void k_edge2(int n) {
    int gw = (blockIdx.x * blockDim.x + threadIdx.x) >> 5;
    if (gw >= n) return;
    int lane = threadIdx.x & 31;
    int g = lane >> 3, l8 = lane & 7;   // 4 edge groups x 8 lanes
    float aD = g_adst2[gw];
    int start = g_off[gw], deg = g_deg[gw];

    float4 acc = make_float4(0.f, 0.f, 0.f, 0.f);
    float psum = 0.f;
    for (int i = g; i < deg; i += 4) {
        int src = g_sorted[start + i];
        float e = g_asrc2[src] + aD;
        e = fmaxf(e, 0.2f * e);
        float p = __expf(e);
        float4 v = reinterpret_cast<const float4*>(g_h2)[src * 8 + l8];
        acc.x += p * v.x; acc.y += p * v.y;
        acc.z += p * v.z; acc.w += p * v.w;
        psum += p;
    }
    #pragma unroll
    for (int o = 8; o <= 16; o <<= 1) {
        acc.x += __shfl_xor_sync(0xffffffffu, acc.x, o);
        acc.y += __shfl_xor_sync(0xffffffffu, acc.y, o);
        acc.z += __shfl_xor_sync(0xffffffffu, acc.z, o);
        acc.w += __shfl_xor_sync(0xffffffffu, acc.w, o);
        psum  += __shfl_xor_sync(0xffffffffu, psum,  o);
    }
    float inv = 1.0f / psum;
    acc.x *= inv; acc.y *= inv; acc.z *= inv; acc.w *= inv;
    if (lane < 8)
        reinterpret_cast<float4*>(g_out2)[gw * 8 + lane] = acc;
}

// ---------------- K5: global sum --------------------------------------------
__global__ void k_final(const float* __restrict__ b2, int n) {
    __shared__ float sd[256];
    int t = threadIdx.x, c = t & 31, g = t >> 5;
    float local = 0.f;
    for (int node = blockIdx.x * 8 + g; node < n; node += gridDim.x * 8)
        local += g_out2[node * C2 + c] + b2[c];
    sd[t] = local;
    __syncthreads();
    if (t < 128) sd[t] += sd[t + 128];
    __syncthreads();
    if (t < 64) sd[t] += sd[t + 64];
    __syncthreads();
    if (t < 32) atomicAdd(&g_accum[c], sd[t] + sd[t + 32]);
}

// ---------------- K6: mean -> logits -> softmax ------------------------------
__global__ void k_out(const float* __restrict__ linW, const float* __restrict__ linb,
                      float* __restrict__ out, int n) {
    if (threadIdx.x == 0) {
        float logits[CLS];
        float invn = 1.0f / (float)n;
        for (int j = 0; j < CLS; j++) {
            float s = linb[j];
            for (int c = 0; c < C2; c++)
                s += (g_accum[c] * invn) * linW[c * CLS + j];
            logits[j] = s;
        }
        float m = fmaxf(logits[0], fmaxf(logits[1], logits[2]));
        float e0 = expf(logits[0] - m);
        float e1 = expf(logits[1] - m);
        float e2 = expf(logits[2] - m);
        float s = e0 + e1 + e2;
        out[0] = e0 / s; out[1] = e1 / s; out[2] = e2 / s;
    }
}

// ---------------- launcher ---------------------------------------------------
extern "C" void kernel_launch(void* const* d_in, const int* in_sizes, int n_in,
                              void* d_out, int out_size) {
    const float* x        = (const float*)d_in[0];
    const float* W1       = (const float*)d_in[1];
    const float* att_src1 = (const float*)d_in[2];
    const float* att_dst1 = (const float*)d_in[3];
    const float* b1       = (const float*)d_in[4];
    const float* W2       = (const float*)d_in[5];
    const float* att_src2 = (const float*)d_in[6];
    const float* att_dst2 = (const float*)d_in[7];
    const float* b2       = (const float*)d_in[8];
    const float* linW     = (const float*)d_in[9];
    const float* linb     = (const float*)d_in[10];
    const int*   ei       = (const int*)d_in[11];

    int n  = in_sizes[0] / F_IN;       // 50000
    int E  = in_sizes[11] / 2;         // 800000
    int ET = E + n;
    int NB = (n + 255) / 256;          // scan blocks (196)
    float* out = (float*)d_out;

    k_detect<<<1, 32>>>(ei);
    k_init<<<64, 256>>>(n);
    k_hist<<<(ET + 255) / 256, 256>>>(ei, E, ET);
    k_scan1<<<NB, 256>>>(n);
    k_scan2<<<1, 256>>>(NB);
    k_scan3<<<NB, 256>>>(n);
    k_scatter<<<(ET + 255) / 256, 256>>>(ei, E, ET);

    k_gemm1<<<(n + 63) / 64, 128>>>(x, W1, att_src1, att_dst1, n);

    {
        long long threads = (long long)n * 32;
        k_edge1<<<(int)((threads + 255) / 256), 256>>>(n);
    }

    k_node1<<<(n + 15) / 16, dim3(32, 8)>>>(W2, b1, att_src2, att_dst2, n);

    {
        long long threads = (long long)n * 32;
        k_edge2<<<(int)((threads + 255) / 256), 256>>>(n);
    }

    k_final<<<512, 256>>>(b2, n);
    k_out<<<1, 32>>>(linW, linb, out, n);
}